// round 2
// baseline (speedup 1.0000x reference)
#include <cuda_runtime.h>
#include <math.h>

#define NB   2
#define CIN  256     // deform output channels O
#define CMID 128     // transconv output channels C
#define H0   64
#define W0   64
#define H    128
#define W    128
#define KK   9
#define KC   1152    // KK * CMID
#define NPIX 16384   // H*W
#define QTOT 32768   // NB * NPIX

// ---------------- device scratch (no mallocs allowed) ----------------
__device__ float g_up[NB][CMID][H][W];        // transposed-conv output
__device__ float g_S[KC][NB][H][W];           // bilinear-sampled im2col (GEMM B)
__device__ float g_Wt[KC][CIN];               // GEMM A, K-major: [k*128+c][o]
__device__ float g_WB[CIN][KK][CMID];         // transconv weights [ci][tap][co]
__device__ int   g_tiy[NB][KK];
__device__ int   g_tix[NB][KK];
__device__ float g_twgt[NB][KK][4];

// ---------------- kernel A: offset net + tap precompute ----------------
__global__ void k_offsets(const float* __restrict__ lat,
                          const float* __restrict__ w1, const float* __restrict__ b1,
                          const float* __restrict__ w2, const float* __restrict__ b2) {
    __shared__ float sh[NB][64];
    __shared__ float soff[NB][18];
    int t = threadIdx.x;                 // 128 threads
    int n = t >> 6, o = t & 63;
    // conv2d(lateral[1x1], w1, pad=1): only center tap (1,1) contributes
    float acc = b1[o];
    for (int i = 0; i < CMID; i++)
        acc += lat[n * CMID + i] * w1[(o * CMID + i) * KK + 4];
    sh[n][o] = fmaxf(acc, 0.f);
    __syncthreads();
    if (t < NB * 18) {
        int nn = t / 18, j = t % 18;
        float a = b2[j];
        for (int q = 0; q < 64; q++)
            a += sh[nn][q] * w2[(j * 64 + q) * KK + 4];
        soff[nn][j] = tanhf(a);
    }
    __syncthreads();
    if (t < NB * KK) {
        int nn = t / KK, k = t % KK;
        float oy = soff[nn][2 * k], ox = soff[nn][2 * k + 1];
        float ay = (float)(k / 3 - 1) + oy;   // pad = 1
        float ax = (float)(k % 3 - 1) + ox;
        float fy = floorf(ay), fx = floorf(ax);
        float dy = ay - fy, dx = ax - fx;
        g_tiy[nn][k] = (int)fy;
        g_tix[nn][k] = (int)fx;
        g_twgt[nn][k][0] = (1.f - dy) * (1.f - dx);
        g_twgt[nn][k][1] = (1.f - dy) * dx;
        g_twgt[nn][k][2] = dy * (1.f - dx);
        g_twgt[nn][k][3] = dy * dx;
    }
}

// ---------------- weight re-layout ----------------
__global__ void k_wprep(const float* __restrict__ w) {
    int e = blockIdx.x * 256 + threadIdx.x;   // < 294912
    {   // GEMM A: g_Wt[kc][o] = w[(o*128 + c)*9 + k], kc = k*128 + c
        int kc = e >> 8;          // e / 256
        int o  = e & 255;
        int c  = kc & 127, k = kc >> 7;
        g_Wt[kc][o] = w[(o * CMID + c) * KK + k];
    }
    {   // transconv: g_WB[ci][tap][co]
        int ci  = e / KC;
        int r   = e - ci * KC;
        int tap = r >> 7;         // r / 128
        int co  = r & 127;
        g_WB[ci][tap][co] = w[(ci * CMID + co) * KK + tap];
    }
}

// ---------------- kernel B: stride-2 transposed conv (parity decomposed) ----------------
// up[n,co,Y,X] = sum_ci sum_{ky,kx: Y=2i+ky-1, X=2j+kx-1} x[n,ci,i,j] * w[ci,co,ky,kx]
#define VBODY(XR, KYV) do {                                                          \
    int kyb = (KYV) * 3;                                                             \
    float wreg[8];                                                                   \
    _Pragma("unroll") for (int c = 0; c < 8; c++) wreg[c] = sW[cc][kyb + 1][co0 + c];\
    _Pragma("unroll") for (int p = 0; p < 8; p += 2) {                               \
        float xv = XR[p >> 1];                                                       \
        _Pragma("unroll") for (int c = 0; c < 8; c++)                                \
            acc[c][p] = fmaf(xv, wreg[c], acc[c][p]);                                \
    }                                                                                \
    _Pragma("unroll") for (int c = 0; c < 8; c++) wreg[c] = sW[cc][kyb + 0][co0 + c];\
    _Pragma("unroll") for (int p = 1; p < 8; p += 2) {                               \
        float xv = XR[(p + 1) >> 1];                                                 \
        _Pragma("unroll") for (int c = 0; c < 8; c++)                                \
            acc[c][p] = fmaf(xv, wreg[c], acc[c][p]);                                \
    }                                                                                \
    _Pragma("unroll") for (int c = 0; c < 8; c++) wreg[c] = sW[cc][kyb + 2][co0 + c];\
    _Pragma("unroll") for (int p = 1; p < 8; p += 2) {                               \
        float xv = XR[p >> 1];                                                       \
        _Pragma("unroll") for (int c = 0; c < 8; c++)                                \
            acc[c][p] = fmaf(xv, wreg[c], acc[c][p]);                                \
    }                                                                                \
} while (0)

__global__ __launch_bounds__(256, 2) void k_transconv(const float* __restrict__ x) {
    const int Y = blockIdx.x;
    const int n = blockIdx.y;
    const int t = threadIdx.x;
    const int xg = t & 15, cg = t >> 4;
    const int X0 = xg << 3, co0 = cg << 3, jb = xg << 2;

    int nv, vky0, vi0, vky1 = 0, vi1 = 0;
    if ((Y & 1) == 0) { nv = 1; vky0 = 1; vi0 = Y >> 1; }
    else {
        int ia = (Y + 1) >> 1;
        if (ia < H0) { nv = 2; vky0 = 0; vi0 = ia; vky1 = 2; vi1 = Y >> 1; }
        else         { nv = 1; vky0 = 2; vi0 = Y >> 1; }
    }

    __shared__ float sX[8][2][64];        // [cc][v][j]
    __shared__ float sW[8][KK][CMID];     // [cc][tap][co]

    float acc[8][8];
    #pragma unroll
    for (int c = 0; c < 8; c++)
        #pragma unroll
        for (int p = 0; p < 8; p++) acc[c][p] = 0.f;

    const float* wb = &g_WB[0][0][0];

    for (int ci0 = 0; ci0 < CIN; ci0 += 8) {
        __syncthreads();
        {   // stage x rows
            int sh = (nv == 2) ? 7 : 6;
            int tot = 8 << sh;
            for (int e = t; e < tot; e += 256) {
                int cc = e >> sh;
                int rr = e & ((1 << sh) - 1);
                int v  = rr >> 6, j = rr & 63;
                int irow = v ? vi1 : vi0;
                sX[cc][v][j] = x[((n * CIN + ci0 + cc) * H0 + irow) * W0 + j];
            }
        }
        {   // stage weights (g_WB is contiguous in [ci][tap][co])
            const float* src = wb + ci0 * (KK * CMID);
            float* dst = &sW[0][0][0];
            for (int e = t; e < 8 * KK * CMID; e += 256) dst[e] = src[e];
        }
        __syncthreads();

        #pragma unroll
        for (int cc = 0; cc < 8; cc++) {
            float xr0[5], xr1[5];
            #pragma unroll
            for (int u = 0; u < 5; u++) {
                int j = jb + u;
                xr0[u] = (j < W0) ? sX[cc][0][j] : 0.f;
                xr1[u] = (nv > 1 && j < W0) ? sX[cc][1][j] : 0.f;
            }
            VBODY(xr0, vky0);
            if (nv > 1) VBODY(xr1, vky1);
        }
    }

    #pragma unroll
    for (int c = 0; c < 8; c++) {
        float* dst = &g_up[n][co0 + c][Y][X0];
        reinterpret_cast<float4*>(dst)[0] =
            make_float4(acc[c][0], acc[c][1], acc[c][2], acc[c][3]);
        reinterpret_cast<float4*>(dst)[1] =
            make_float4(acc[c][4], acc[c][5], acc[c][6], acc[c][7]);
    }
}

// ---------------- kernel C1: bilinear gather (spatially uniform offsets) ----------------
__global__ void k_sample() {
    int idx = blockIdx.x * 256 + threadIdx.x;   // 9,437,184 threads, 4 elems each
    int e = idx << 2;
    int x0 = e & 127;
    int y  = (e >> 7) & 127;
    int n  = (e >> 14) & 1;
    int kc = e >> 15;                  // 0..1151
    int c  = kc & 127, k = kc >> 7;

    int iy = g_tiy[n][k], ix = g_tix[n][k];
    float w00 = g_twgt[n][k][0], w01 = g_twgt[n][k][1];
    float w10 = g_twgt[n][k][2], w11 = g_twgt[n][k][3];

    const float* U = &g_up[n][c][0][0];
    int r0 = y + iy, r1 = r0 + 1;
    bool v0 = (r0 >= 0) && (r0 < H);
    bool v1 = (r1 >= 0) && (r1 < H);
    int cb = x0 + ix;

    float row0[5], row1[5];
    #pragma unroll
    for (int u = 0; u < 5; u++) {
        int col = cb + u;
        bool vc = (col >= 0) && (col < W);
        row0[u] = (v0 && vc) ? U[r0 * W + col] : 0.f;
        row1[u] = (v1 && vc) ? U[r1 * W + col] : 0.f;
    }
    float4 o;
    o.x = w00 * row0[0] + w01 * row0[1] + w10 * row1[0] + w11 * row1[1];
    o.y = w00 * row0[1] + w01 * row0[2] + w10 * row1[1] + w11 * row1[2];
    o.z = w00 * row0[2] + w01 * row0[3] + w10 * row1[2] + w11 * row1[3];
    o.w = w00 * row0[3] + w01 * row0[4] + w10 * row1[3] + w11 * row1[4];

    float* dst = &g_S[kc][n][y][x0];
    *reinterpret_cast<float4*>(dst) = o;
}

// ---------------- kernel C2: SGEMM  C[o][q] = sum_kc A[kc][o] * B[kc][q] ----------------
__global__ __launch_bounds__(256) void k_gemm(float* __restrict__ out) {
    const int nb = blockIdx.x;   // N blocks of 128 (256 total)
    const int mb = blockIdx.y;   // M blocks of 128 (2 total)
    const int t  = threadIdx.x;
    const int tm = t >> 4, tn = t & 15;
    const int m0 = mb * 128, n0 = nb * 128;

    __shared__ float As[2][8][128];
    __shared__ float Bs[2][8][128];

    const float* Ag = &g_Wt[0][0];          // [KC][256]
    const float* Bg = &g_S[0][0][0][0];     // [KC][32768]

    const int la_k = t >> 5;                // 0..7
    const int la_m = (t << 2) & 127;        // 0..124 step 4

    float acc[8][8];
    #pragma unroll
    for (int i = 0; i < 8; i++)
        #pragma unroll
        for (int j = 0; j < 8; j++) acc[i][j] = 0.f;

    {   // preload chunk 0
        float4 a = *(const float4*)&Ag[la_k * CIN + m0 + la_m];
        float4 b = *(const float4*)&Bg[(size_t)la_k * QTOT + n0 + la_m];
        *(float4*)&As[0][la_k][la_m] = a;
        *(float4*)&Bs[0][la_k][la_m] = b;
    }
    __syncthreads();

    const int NT = KC / 8;   // 144
    for (int kt = 0; kt < NT; kt++) {
        int cur = kt & 1;
        float4 pa, pb;
        bool more = (kt + 1 < NT);
        if (more) {
            int k0 = (kt + 1) * 8;
            pa = *(const float4*)&Ag[(k0 + la_k) * CIN + m0 + la_m];
            pb = *(const float4*)&Bg[(size_t)(k0 + la_k) * QTOT + n0 + la_m];
        }
        #pragma unroll
        for (int kk = 0; kk < 8; kk++) {
            float a[8], b[8];
            *(float4*)&a[0] = *(const float4*)&As[cur][kk][tm * 8];
            *(float4*)&a[4] = *(const float4*)&As[cur][kk][tm * 8 + 4];
            *(float4*)&b[0] = *(const float4*)&Bs[cur][kk][tn * 8];
            *(float4*)&b[4] = *(const float4*)&Bs[cur][kk][tn * 8 + 4];
            #pragma unroll
            for (int i = 0; i < 8; i++)
                #pragma unroll
                for (int j = 0; j < 8; j++)
                    acc[i][j] = fmaf(a[i], b[j], acc[i][j]);
        }
        if (more) {
            int nxt = cur ^ 1;
            *(float4*)&As[nxt][la_k][la_m] = pa;
            *(float4*)&Bs[nxt][la_k][la_m] = pb;
        }
        __syncthreads();
    }

    // epilogue: q = n*16384 + pix ; out[n][o][pix]
    int nbat = n0 >> 14;
    int pix0 = (n0 & 16383) + tn * 8;
    #pragma unroll
    for (int i = 0; i < 8; i++) {
        int o = m0 + tm * 8 + i;
        float* dst = out + ((size_t)nbat * CIN + o) * NPIX + pix0;
        *(float4*)&dst[0] = make_float4(acc[i][0], acc[i][1], acc[i][2], acc[i][3]);
        *(float4*)&dst[4] = make_float4(acc[i][4], acc[i][5], acc[i][6], acc[i][7]);
    }
}

// ---------------- launch ----------------
extern "C" void kernel_launch(void* const* d_in, const int* in_sizes, int n_in,
                              void* d_out, int out_size) {
    const float* x   = (const float*)d_in[0];   // [2,256,64,64]
    const float* lat = (const float*)d_in[1];   // [2,128,1,1]
    const float* tw  = (const float*)d_in[2];   // [256,128,3,3]
    const float* w1  = (const float*)d_in[3];   // [64,128,3,3]
    const float* b1  = (const float*)d_in[4];   // [64]
    const float* w2  = (const float*)d_in[5];   // [18,64,3,3]
    const float* b2  = (const float*)d_in[6];   // [18]
    float* out = (float*)d_out;                 // [2,256,128,128]

    k_offsets<<<1, 128>>>(lat, w1, b1, w2, b2);
    k_wprep<<<1152, 256>>>(tw);
    k_transconv<<<dim3(128, 2), 256>>>(x);
    k_sample<<<36864, 256>>>();
    k_gemm<<<dim3(256, 2), 256>>>(out);
}